// round 3
// baseline (speedup 1.0000x reference)
#include <cuda_runtime.h>
#include <cstdint>

typedef unsigned long long u64;

// Problem constants
#define B_  16
#define N_  8192
#define C_  256
#define K_  4096

// Output layout (float32): [features][indices][adjacency][scores]
#define OFF_FEAT   ((size_t)0)
#define OFF_IDX    ((size_t)B_ * K_ * C_)
#define OFF_ADJ    (OFF_IDX + (size_t)B_ * K_)
#define OFF_SCORES (OFF_ADJ + (size_t)B_ * K_ * K_)

// Scratch (device globals; no allocation allowed)
__device__ __align__(16) unsigned short g_idx[B_ * K_];
__device__ int g_pos[B_ * N_];

// ---------------------------------------------------------------------------
// Bitonic helpers.  Convention: at stage (k, j), the lower-index element of a
// pair keeps the max iff (i & k) == 0  (=> final order descending; composite
// key = flipped_score<<16 | (8191-idx) makes ties break by ascending index,
// matching jax.lax.top_k).
// ---------------------------------------------------------------------------
__device__ __forceinline__ void ce_pair(u64 &lo, u64 &hi, bool desc) {
    u64 a = lo, b = hi;
    u64 mx = a > b ? a : b;
    u64 mn = a > b ? b : a;
    lo = desc ? mx : mn;
    hi = desc ? mn : mx;
}

__device__ __forceinline__ u64 shfl_ce(u64 v, int j, bool keepmax) {
    u64 o = __shfl_xor_sync(0xFFFFFFFFu, v, j);
    u64 mx = v > o ? v : o;
    u64 mn = v > o ? o : v;
    return keepmax ? mx : mn;
}

// Strided orbit pass: 16 elements at stride S per thread; performs stages
// j = JHI .. JLO (each j a multiple of S, pairs differ in m-bit j/S).
template<int S, int JHI, int JLO, int K>
__device__ __forceinline__ void strided_pass(u64* s, int t)
{
    const int base = (S == 512) ? t : ((t & 255) + (t >> 8) * 4096);
    u64 v[16];
    #pragma unroll
    for (int m = 0; m < 16; m++) v[m] = s[base + m * S];
    #pragma unroll
    for (int j = JHI; j >= JLO; j >>= 1) {
        const int mb = j / S;
        #pragma unroll
        for (int m = 0; m < 16; m++) {
            if (!(m & mb)) {
                bool desc = (((base + m * S) & K) == 0);
                ce_pair(v[m], v[m | mb], desc);
            }
        }
    }
    #pragma unroll
    for (int m = 0; m < 16; m++) s[base + m * S] = v[m];
}

// Blocked pass: i = wbase + e*32 + l.  Reg stages j = JSTART..32 (e-bits),
// then shuffle stages j = 16..1 (lane bits).
template<int JSTART, int K>
__device__ __forceinline__ void blocked_pass(u64* s, int wbase, int l)
{
    u64 v[16];
    #pragma unroll
    for (int e = 0; e < 16; e++) v[e] = s[wbase + e * 32 + l];
    #pragma unroll
    for (int eb = JSTART >> 5; eb >= 1; eb >>= 1) {
        #pragma unroll
        for (int e = 0; e < 16; e++) {
            if (!(e & eb)) {
                bool desc = (((wbase + e * 32 + l) & K) == 0);
                ce_pair(v[e], v[e | eb], desc);
            }
        }
    }
    #pragma unroll
    for (int j = 16; j >= 1; j >>= 1) {
        #pragma unroll
        for (int e = 0; e < 16; e++) {
            bool desc = (((wbase + e * 32 + l) & K) == 0);
            v[e] = shfl_ce(v[e], j, desc == ((l & j) == 0));
        }
    }
    #pragma unroll
    for (int e = 0; e < 16; e++) s[wbase + e * 32 + l] = v[e];
}

// ---------------------------------------------------------------------------
// Kernel 1: per-batch descending sort of u64 composites, one CTA per batch.
// ---------------------------------------------------------------------------
__global__ __launch_bounds__(512, 1)
void topk_kernel(const float* __restrict__ scores,
                 float* __restrict__ out_idxf,
                 float* __restrict__ out_scores)
{
    extern __shared__ u64 s[];          // 8192 * 8B = 64 KB
    const int b = blockIdx.x;
    const float* sc = scores + (size_t)b * N_;
    const int t = threadIdx.x;
    const int l = t & 31;
    const int wbase = (t >> 5) * 512;

    // ---- P0: load from gmem, build keys, clear pos map, sort k=2..512 ----
    u64 v[16];
    #pragma unroll
    for (int e = 0; e < 16; e++) {
        int i = wbase + e * 32 + l;
        unsigned u = __float_as_uint(sc[i]);
        u ^= (u & 0x80000000u) ? 0xFFFFFFFFu : 0x80000000u;   // order-preserving flip
        v[e] = ((u64)u << 16) | (unsigned)(8191 - i);
        g_pos[b * N_ + t * 16 + e] = -1;
    }

    #pragma unroll
    for (int kk = 2; kk <= 512; kk <<= 1) {
        #pragma unroll
        for (int eb = 8; eb >= 1; eb >>= 1) {
            const int j = eb << 5;
            if (j < kk) {
                #pragma unroll
                for (int e = 0; e < 16; e++) {
                    if (!(e & eb)) {
                        bool desc = (((wbase + e * 32 + l) & kk) == 0);
                        ce_pair(v[e], v[e | eb], desc);
                    }
                }
            }
        }
        #pragma unroll
        for (int j = 16; j >= 1; j >>= 1) {
            if (j < kk) {
                #pragma unroll
                for (int e = 0; e < 16; e++) {
                    bool desc = (((wbase + e * 32 + l) & kk) == 0);
                    v[e] = shfl_ce(v[e], j, desc == ((l & j) == 0));
                }
            }
        }
    }
    #pragma unroll
    for (int e = 0; e < 16; e++) s[wbase + e * 32 + l] = v[e];
    __syncthreads();

    // ---- k = 1024 ----
    strided_pass<256, 512, 256, 1024>(s, t);   __syncthreads();
    blocked_pass<128, 1024>(s, wbase, l);      __syncthreads();
    // ---- k = 2048 ----
    strided_pass<256, 1024, 256, 2048>(s, t);  __syncthreads();
    blocked_pass<128, 2048>(s, wbase, l);      __syncthreads();
    // ---- k = 4096 ----
    strided_pass<256, 2048, 256, 4096>(s, t);  __syncthreads();
    blocked_pass<128, 4096>(s, wbase, l);      __syncthreads();
    // ---- k = 8192 ----
    strided_pass<512, 4096, 512, 8192>(s, t);  __syncthreads();

    // ---- Final blocked stages (j=256..1, all descending) + emit ----
    {
        u64 f[16];
        #pragma unroll
        for (int e = 0; e < 16; e++) f[e] = s[wbase + e * 32 + l];
        #pragma unroll
        for (int eb = 8; eb >= 1; eb >>= 1) {
            #pragma unroll
            for (int e = 0; e < 16; e++)
                if (!(e & eb)) ce_pair(f[e], f[e | eb], true);
        }
        #pragma unroll
        for (int j = 16; j >= 1; j >>= 1) {
            #pragma unroll
            for (int e = 0; e < 16; e++)
                f[e] = shfl_ce(f[e], j, (l & j) == 0);
        }
        if (wbase < K_) {   // first 8 warps hold ranks 0..4095
            #pragma unroll
            for (int e = 0; e < 16; e++) {
                int rank = wbase + e * 32 + l;
                u64 x = f[e];
                int idx = 8191 - (int)(x & 0xFFFF);
                unsigned ku = (unsigned)(x >> 16);
                unsigned orig = (ku & 0x80000000u) ? (ku ^ 0x80000000u) : ~ku;
                g_idx[b * K_ + rank] = (unsigned short)idx;
                out_idxf[(size_t)b * K_ + rank]   = (float)idx;
                out_scores[(size_t)b * K_ + rank] = __uint_as_float(orig);
                g_pos[b * N_ + idx] = rank;
            }
        }
    }
}

// ---------------------------------------------------------------------------
// Kernel 2: gather selected features. out[b][i][:] = features[b][idx[b][i]][:]
// ---------------------------------------------------------------------------
__global__ __launch_bounds__(256)
void feat_kernel(const float4* __restrict__ feat, float4* __restrict__ out)
{
    int o = blockIdx.x * blockDim.x + threadIdx.x;
    int row = o >> 6;                                  // C/4 = 64 float4 per row
    int c   = o & 63;
    int b   = row >> 12;                               // K = 4096 rows per batch
    int r   = g_idx[row];
    out[o] = feat[((size_t)(b << 13) + r) * 64 + c];   // N = 8192 rows per batch
}

// ---------------------------------------------------------------------------
// Kernel 3: adjacency gather with source-row reuse.
// ---------------------------------------------------------------------------
__global__ __launch_bounds__(512)
void adj_kernel(const float* __restrict__ A, float* __restrict__ out)
{
    __shared__ float row[N_];   // 32 KB
    const int r = blockIdx.x;

    const float4* src  = (const float4*)(A + (size_t)r * N_);
    float4*       rowv = (float4*)row;
    for (int t = threadIdx.x; t < N_ / 4; t += blockDim.x)
        rowv[t] = src[t];
    __syncthreads();

    #pragma unroll 1
    for (int b = 0; b < B_; ++b) {
        int i = g_pos[b * N_ + r];
        if (i < 0) continue;
        float4* obase = (float4*)(out + ((size_t)b * K_ + i) * K_);
        const ushort4* idx4 = (const ushort4*)(g_idx + b * K_);
        for (int t = threadIdx.x; t < K_ / 4; t += blockDim.x) {
            ushort4 c = idx4[t];
            obase[t] = make_float4(row[c.x], row[c.y], row[c.z], row[c.w]);
        }
    }
}

// ---------------------------------------------------------------------------
extern "C" void kernel_launch(void* const* d_in, const int* in_sizes, int n_in,
                              void* d_out, int out_size)
{
    const float* scores = (const float*)d_in[0];   // (B, N)
    const float* feat   = (const float*)d_in[1];   // (B, N, C)
    const float* adj    = (const float*)d_in[2];   // (N, N)
    float* out = (float*)d_out;

    float* out_feat   = out + OFF_FEAT;
    float* out_idxf   = out + OFF_IDX;
    float* out_adj    = out + OFF_ADJ;
    float* out_scores = out + OFF_SCORES;

    static bool attr_set = false;
    if (!attr_set) {
        cudaFuncSetAttribute(topk_kernel,
                             cudaFuncAttributeMaxDynamicSharedMemorySize,
                             N_ * sizeof(u64));
        attr_set = true;
    }

    topk_kernel<<<B_, 512, N_ * sizeof(u64)>>>(scores, out_idxf, out_scores);

    int n_f4 = (B_ * K_ * C_) / 4;
    feat_kernel<<<n_f4 / 256, 256>>>((const float4*)feat, (float4*)out_feat);

    adj_kernel<<<N_, 512>>>(adj, out_adj);
}

// round 4
// speedup vs baseline: 1.1985x; 1.1985x over previous
#include <cuda_runtime.h>
#include <cstdint>

typedef unsigned long long u64;

#define B_  16
#define N_  8192
#define C_  256
#define K_  4096

// Output layout (float32): [features][indices][adjacency][scores]
#define OFF_FEAT   ((size_t)0)
#define OFF_IDX    ((size_t)B_ * K_ * C_)
#define OFF_ADJ    (OFF_IDX + (size_t)B_ * K_)
#define OFF_SCORES (OFF_ADJ + (size_t)B_ * K_ * K_)

// Scratch (device globals; no allocation allowed)
__device__ __align__(16) unsigned short g_idx[B_ * K_];
__device__ int g_pos[B_ * N_];
__device__ __align__(16) u64 g_keys[B_ * N_];      // 1 MB sort scratch

// ---------------------------------------------------------------------------
// Bitonic convention: at stage (k, j), the lower element of a pair keeps the
// max iff (i & k)==0  => final order descending.  Composite key
// flipped_score<<16 | (8191-idx) makes ties break by ascending index.
// ---------------------------------------------------------------------------
__device__ __forceinline__ void ce_pair(u64 &lo, u64 &hi, bool desc) {
    u64 a = lo, b = hi;
    u64 mx = a > b ? a : b;
    u64 mn = a > b ? b : a;
    lo = desc ? mx : mn;
    hi = desc ? mn : mx;
}
__device__ __forceinline__ u64 shfl_ce(u64 v, int j, bool keepmax) {
    u64 o = __shfl_xor_sync(0xFFFFFFFFu, v, j);
    u64 mx = v > o ? v : o;
    u64 mn = v > o ? o : v;
    return keepmax ? mx : mn;
}
__device__ __forceinline__ void smem_ce(u64* s, int i, int m, bool desc) {
    u64 a = s[i], c = s[m];
    if ((a < c) == desc) { s[i] = c; s[m] = a; }
}

// ---------------------------------------------------------------------------
// K1: sort each 1024-chunk (k=2..1024). grid B*8, block 256, 4 u64/thread.
// Also builds keys from scores and clears g_pos.
// ---------------------------------------------------------------------------
__global__ __launch_bounds__(256)
void sort1024_kernel(const float* __restrict__ scores)
{
    __shared__ u64 s[1024];
    const int b  = blockIdx.x >> 3;
    const int cb = (blockIdx.x & 7) << 10;          // batch-local chunk base
    const int t  = threadIdx.x;
    const int l  = t & 31;
    const int wbase = (t >> 5) << 7;                // warp*128
    const float* sc = scores + (size_t)b * N_;

    u64 v[4];
    #pragma unroll
    for (int e = 0; e < 4; e++) {
        int I = cb + wbase + e * 32 + l;            // batch-local index
        unsigned u = __float_as_uint(sc[I]);
        u ^= (u & 0x80000000u) ? 0xFFFFFFFFu : 0x80000000u;
        v[e] = ((u64)u << 16) | (unsigned)(8191 - I);
        g_pos[b * N_ + cb + e * 256 + t] = -1;
    }

    // ---- register phase: k = 2..128 ----
    #pragma unroll
    for (int k = 2; k <= 128; k <<= 1) {
        #pragma unroll
        for (int eb = 2; eb >= 1; eb >>= 1) {
            const int j = eb << 5;
            if (j < k) {
                #pragma unroll
                for (int e = 0; e < 4; e++)
                    if (!(e & eb)) {
                        bool desc = (((cb + wbase + e * 32) & k) == 0);
                        ce_pair(v[e], v[e | eb], desc);
                    }
            }
        }
        #pragma unroll
        for (int j = 16; j >= 1; j >>= 1) {
            if (j < k) {
                #pragma unroll
                for (int e = 0; e < 4; e++) {
                    bool desc = (((cb + wbase + e * 32 + l) & k) == 0);
                    v[e] = shfl_ce(v[e], j, desc == ((l & j) == 0));
                }
            }
        }
    }

    // ---- k = 256, 512, 1024: smem stages j>=128, register tail j<=64 ----
    #pragma unroll 1
    for (int k = 256; k <= 1024; k <<= 1) {
        #pragma unroll
        for (int e = 0; e < 4; e++) s[wbase + e * 32 + l] = v[e];
        __syncthreads();
        #pragma unroll 1
        for (int j = k >> 1; j >= 128; j >>= 1) {
            #pragma unroll
            for (int q = 0; q < 2; q++) {
                int p = t + q * 256;                       // 0..511
                int i = ((p & ~(j - 1)) << 1) | (p & (j - 1));
                bool desc = (((cb + i) & k) == 0);
                smem_ce(s, i, i + j, desc);
            }
            __syncthreads();
        }
        #pragma unroll
        for (int e = 0; e < 4; e++) v[e] = s[wbase + e * 32 + l];
        __syncthreads();
        #pragma unroll
        for (int eb = 2; eb >= 1; eb >>= 1) {
            #pragma unroll
            for (int e = 0; e < 4; e++)
                if (!(e & eb)) {
                    bool desc = (((cb + wbase + e * 32) & k) == 0);
                    ce_pair(v[e], v[e | eb], desc);
                }
        }
        #pragma unroll
        for (int j = 16; j >= 1; j >>= 1) {
            #pragma unroll
            for (int e = 0; e < 4; e++) {
                bool desc = (((cb + wbase + e * 32 + l) & k) == 0);
                v[e] = shfl_ce(v[e], j, desc == ((l & j) == 0));
            }
        }
    }

    #pragma unroll
    for (int e = 0; e < 4; e++)
        g_keys[(size_t)b * N_ + cb + wbase + e * 32 + l] = v[e];
}

// ---------------------------------------------------------------------------
// K2: k=2048 merge in 2048-windows. grid B*4, block 512, 4 u64/thread.
// ---------------------------------------------------------------------------
__global__ __launch_bounds__(512)
void merge2048_kernel()
{
    __shared__ u64 s[2048];
    const int b    = blockIdx.x >> 2;
    const int base = (blockIdx.x & 3) << 11;
    const bool desc = ((base & 2048) == 0);
    const int t = threadIdx.x;
    const int l = t & 31;
    const int wbase = (t >> 5) << 7;
    u64* gk = g_keys + (size_t)b * N_ + base;

    for (int x = t; x < 2048; x += 512) s[x] = gk[x];
    __syncthreads();

    #pragma unroll 1
    for (int j = 1024; j >= 128; j >>= 1) {
        #pragma unroll
        for (int q = 0; q < 2; q++) {
            int p = t + q * 512;                          // 0..1023
            int i = ((p & ~(j - 1)) << 1) | (p & (j - 1));
            smem_ce(s, i, i + j, desc);
        }
        __syncthreads();
    }

    u64 v[4];
    #pragma unroll
    for (int e = 0; e < 4; e++) v[e] = s[wbase + e * 32 + l];
    #pragma unroll
    for (int eb = 2; eb >= 1; eb >>= 1)
        #pragma unroll
        for (int e = 0; e < 4; e++)
            if (!(e & eb)) ce_pair(v[e], v[e | eb], desc);
    #pragma unroll
    for (int j = 16; j >= 1; j >>= 1)
        #pragma unroll
        for (int e = 0; e < 4; e++)
            v[e] = shfl_ce(v[e], j, desc == ((l & j) == 0));
    #pragma unroll
    for (int e = 0; e < 4; e++) gk[wbase + e * 32 + l] = v[e];
}

// ---------------------------------------------------------------------------
// K3: k=4096 merge in 4096-windows. grid B*2, block 512, 8 u64/thread.
// ---------------------------------------------------------------------------
__global__ __launch_bounds__(512)
void merge4096_kernel()
{
    __shared__ u64 s[4096];
    const int b    = blockIdx.x >> 1;
    const int base = (blockIdx.x & 1) << 12;
    const bool desc = ((base & 4096) == 0);
    const int t = threadIdx.x;
    const int l = t & 31;
    const int wbase = (t >> 5) << 8;                  // warp*256
    u64* gk = g_keys + (size_t)b * N_ + base;

    for (int x = t; x < 4096; x += 512) s[x] = gk[x];
    __syncthreads();

    #pragma unroll 1
    for (int j = 2048; j >= 256; j >>= 1) {
        #pragma unroll
        for (int q = 0; q < 4; q++) {
            int p = t + q * 512;                          // 0..2047
            int i = ((p & ~(j - 1)) << 1) | (p & (j - 1));
            smem_ce(s, i, i + j, desc);
        }
        __syncthreads();
    }

    u64 v[8];
    #pragma unroll
    for (int e = 0; e < 8; e++) v[e] = s[wbase + e * 32 + l];
    #pragma unroll
    for (int eb = 4; eb >= 1; eb >>= 1)
        #pragma unroll
        for (int e = 0; e < 8; e++)
            if (!(e & eb)) ce_pair(v[e], v[e | eb], desc);
    #pragma unroll
    for (int j = 16; j >= 1; j >>= 1)
        #pragma unroll
        for (int e = 0; e < 8; e++)
            v[e] = shfl_ce(v[e], j, desc == ((l & j) == 0));
    #pragma unroll
    for (int e = 0; e < 8; e++) gk[wbase + e * 32 + l] = v[e];
}

// ---------------------------------------------------------------------------
// K4: k=8192 stages j=4096,2048,1024 as register orbits (desc=true).
// grid B*4, block 256; thread owns 8 elems at stride 1024, coalesced.
// ---------------------------------------------------------------------------
__global__ __launch_bounds__(256)
void orbit8192_kernel()
{
    const int b = blockIdx.x >> 2;
    const int q = ((blockIdx.x & 3) << 8) + threadIdx.x;   // 0..1023
    u64* gk = g_keys + (size_t)b * N_ + q;

    u64 v[8];
    #pragma unroll
    for (int m = 0; m < 8; m++) v[m] = gk[m << 10];
    #pragma unroll
    for (int mb = 4; mb >= 1; mb >>= 1)
        #pragma unroll
        for (int m = 0; m < 8; m++)
            if (!(m & mb)) ce_pair(v[m], v[m | mb], true);
    #pragma unroll
    for (int m = 0; m < 8; m++) gk[m << 10] = v[m];
}

// ---------------------------------------------------------------------------
// K5: k=8192 final stages j=512..1 in 1024-windows (desc=true), only the
// top-4 windows (ranks 0..4095) + emit.  grid B*4, block 256, 4 u64/thread.
// ---------------------------------------------------------------------------
__global__ __launch_bounds__(256)
void finalize_kernel(float* __restrict__ out_idxf,
                     float* __restrict__ out_scores)
{
    __shared__ u64 s[1024];
    const int b    = blockIdx.x >> 2;
    const int base = (blockIdx.x & 3) << 10;          // rank window base
    const int t = threadIdx.x;
    const int l = t & 31;
    const int wbase = (t >> 5) << 7;
    const u64* gk = g_keys + (size_t)b * N_ + base;

    for (int x = t; x < 1024; x += 256) s[x] = gk[x];
    __syncthreads();

    #pragma unroll 1
    for (int j = 512; j >= 128; j >>= 1) {
        #pragma unroll
        for (int q = 0; q < 2; q++) {
            int p = t + q * 256;
            int i = ((p & ~(j - 1)) << 1) | (p & (j - 1));
            smem_ce(s, i, i + j, true);
        }
        __syncthreads();
    }

    u64 v[4];
    #pragma unroll
    for (int e = 0; e < 4; e++) v[e] = s[wbase + e * 32 + l];
    #pragma unroll
    for (int eb = 2; eb >= 1; eb >>= 1)
        #pragma unroll
        for (int e = 0; e < 4; e++)
            if (!(e & eb)) ce_pair(v[e], v[e | eb], true);
    #pragma unroll
    for (int j = 16; j >= 1; j >>= 1)
        #pragma unroll
        for (int e = 0; e < 4; e++)
            v[e] = shfl_ce(v[e], j, (l & j) == 0);

    #pragma unroll
    for (int e = 0; e < 4; e++) {
        int rank = base + wbase + e * 32 + l;
        u64 x = v[e];
        int idx = 8191 - (int)(x & 0xFFFF);
        unsigned ku = (unsigned)(x >> 16);
        unsigned orig = (ku & 0x80000000u) ? (ku ^ 0x80000000u) : ~ku;
        g_idx[b * K_ + rank] = (unsigned short)idx;
        out_idxf[(size_t)b * K_ + rank]   = (float)idx;
        out_scores[(size_t)b * K_ + rank] = __uint_as_float(orig);
        g_pos[b * N_ + idx] = rank;
    }
}

// ---------------------------------------------------------------------------
// Combined gather: blocks [0,8192) do adjacency rows (SMEM-staged source row,
// serving every batch containing it); blocks [8192,16384) do feature gather.
// Single launch => DRAM-bound phases overlap across SMs.
// ---------------------------------------------------------------------------
__global__ __launch_bounds__(512)
void gather_kernel(const float* __restrict__ A,
                   const float4* __restrict__ feat,
                   float* __restrict__ out_adj,
                   float4* __restrict__ out_feat)
{
    __shared__ float row[N_];   // 32 KB (adj branch only)
    if (blockIdx.x < 8192) {
        const int r = blockIdx.x;
        const float4* src  = (const float4*)(A + (size_t)r * N_);
        float4*       rowv = (float4*)row;
        for (int t = threadIdx.x; t < N_ / 4; t += 512)
            rowv[t] = src[t];
        __syncthreads();

        #pragma unroll 1
        for (int b = 0; b < B_; ++b) {
            int i = g_pos[b * N_ + r];
            if (i < 0) continue;
            float4* obase = (float4*)(out_adj + ((size_t)b * K_ + i) * K_);
            const ushort4* idx4 = (const ushort4*)(g_idx + b * K_);
            for (int t = threadIdx.x; t < K_ / 4; t += 512) {
                ushort4 c = idx4[t];
                obase[t] = make_float4(row[c.x], row[c.y], row[c.z], row[c.w]);
            }
        }
    } else {
        int o = (blockIdx.x - 8192) * 512 + threadIdx.x;   // 0..4194303
        int frow = o >> 6;                                  // C/4=64 f4/row
        int c    = o & 63;
        int b    = frow >> 12;                              // K rows/batch
        int r    = g_idx[frow];
        out_feat[o] = feat[((size_t)(b << 13) + r) * 64 + c];
    }
}

// ---------------------------------------------------------------------------
extern "C" void kernel_launch(void* const* d_in, const int* in_sizes, int n_in,
                              void* d_out, int out_size)
{
    const float* scores = (const float*)d_in[0];   // (B, N)
    const float* feat   = (const float*)d_in[1];   // (B, N, C)
    const float* adj    = (const float*)d_in[2];   // (N, N)
    float* out = (float*)d_out;

    float* out_feat   = out + OFF_FEAT;
    float* out_idxf   = out + OFF_IDX;
    float* out_adj    = out + OFF_ADJ;
    float* out_scores = out + OFF_SCORES;

    sort1024_kernel <<<B_ * 8, 256>>>(scores);
    merge2048_kernel<<<B_ * 4, 512>>>();
    merge4096_kernel<<<B_ * 2, 512>>>();
    orbit8192_kernel<<<B_ * 4, 256>>>();
    finalize_kernel <<<B_ * 4, 256>>>(out_idxf, out_scores);

    gather_kernel<<<16384, 512>>>(adj, (const float4*)feat,
                                  out_adj, (float4*)out_feat);
}

// round 5
// speedup vs baseline: 1.2468x; 1.0403x over previous
#include <cuda_runtime.h>
#include <cstdint>

typedef unsigned long long u64;

#define B_  16
#define N_  8192
#define C_  256
#define K_  4096

// Output layout (float32): [features][indices][adjacency][scores]
#define OFF_FEAT   ((size_t)0)
#define OFF_IDX    ((size_t)B_ * K_ * C_)
#define OFF_ADJ    (OFF_IDX + (size_t)B_ * K_)
#define OFF_SCORES (OFF_ADJ + (size_t)B_ * K_ * K_)

// Scratch (device globals; no allocation allowed)
__device__ __align__(16) unsigned short g_idx[B_ * K_];
__device__ int g_pos[B_ * N_];
__device__ __align__(16) u64 g_keys[B_ * N_];      // 1 MB sort scratch

// ---------------------------------------------------------------------------
// Bitonic convention: at stage (k, j), the lower element of a pair keeps the
// max iff (i & k)==0  => final order descending.  Composite key
// flipped_score<<16 | (8191-idx) breaks ties by ascending index (jax.lax.top_k).
// ---------------------------------------------------------------------------
__device__ __forceinline__ void ce_pair(u64 &lo, u64 &hi, bool desc) {
    u64 a = lo, b = hi;
    u64 mx = a > b ? a : b;
    u64 mn = a > b ? b : a;
    lo = desc ? mx : mn;
    hi = desc ? mn : mx;
}
__device__ __forceinline__ u64 shfl_ce(u64 v, int j, bool keepmax) {
    u64 o = __shfl_xor_sync(0xFFFFFFFFu, v, j);
    u64 mx = v > o ? v : o;
    u64 mn = v > o ? o : v;
    return keepmax ? mx : mn;
}
__device__ __forceinline__ void smem_ce(u64* s, int i, int m, bool desc) {
    u64 a = s[i], c = s[m];
    if ((a < c) == desc) { s[i] = c; s[m] = a; }
}

// ---------------------------------------------------------------------------
// K1: sort each 2048-chunk (k=2..2048). grid B*4, block 512, 4 u64/thread,
// 16KB smem. Builds keys from scores and clears g_pos.
// ---------------------------------------------------------------------------
__global__ __launch_bounds__(512)
void sort2048_kernel(const float* __restrict__ scores)
{
    __shared__ u64 s[2048];
    const int b  = blockIdx.x >> 2;
    const int cb = (blockIdx.x & 3) << 11;          // batch-local chunk base
    const int t  = threadIdx.x;
    const int l  = t & 31;
    const int wbase = (t >> 5) << 7;                // warp*128
    const float* sc = scores + (size_t)b * N_;

    u64 v[4];
    #pragma unroll
    for (int e = 0; e < 4; e++) {
        int I = cb + wbase + e * 32 + l;
        unsigned u = __float_as_uint(sc[I]);
        u ^= (u & 0x80000000u) ? 0xFFFFFFFFu : 0x80000000u;
        v[e] = ((u64)u << 16) | (unsigned)(8191 - I);
        g_pos[b * N_ + cb + e * 512 + t] = -1;
    }

    // ---- register phase: k = 2..128 (within each 128-elem blocked group) --
    #pragma unroll
    for (int k = 2; k <= 128; k <<= 1) {
        #pragma unroll
        for (int eb = 2; eb >= 1; eb >>= 1) {
            const int j = eb << 5;
            if (j < k) {
                #pragma unroll
                for (int e = 0; e < 4; e++)
                    if (!(e & eb)) {
                        bool desc = (((cb + wbase + e * 32) & k) == 0);
                        ce_pair(v[e], v[e | eb], desc);
                    }
            }
        }
        #pragma unroll
        for (int j = 16; j >= 1; j >>= 1) {
            if (j < k) {
                #pragma unroll
                for (int e = 0; e < 4; e++) {
                    bool desc = (((cb + wbase + e * 32 + l) & k) == 0);
                    v[e] = shfl_ce(v[e], j, desc == ((l & j) == 0));
                }
            }
        }
    }

    // ---- k = 256..2048: smem stages j>=128, register tail j<=64 ----
    #pragma unroll 1
    for (int k = 256; k <= 2048; k <<= 1) {
        #pragma unroll
        for (int e = 0; e < 4; e++) s[wbase + e * 32 + l] = v[e];
        __syncthreads();
        #pragma unroll 1
        for (int j = k >> 1; j >= 128; j >>= 1) {
            #pragma unroll
            for (int q = 0; q < 2; q++) {
                int p = t + q * 512;                       // 0..1023
                int i = ((p & ~(j - 1)) << 1) | (p & (j - 1));
                bool desc = (((cb + i) & k) == 0);
                smem_ce(s, i, i + j, desc);
            }
            __syncthreads();
        }
        #pragma unroll
        for (int e = 0; e < 4; e++) v[e] = s[wbase + e * 32 + l];
        __syncthreads();
        #pragma unroll
        for (int eb = 2; eb >= 1; eb >>= 1) {
            #pragma unroll
            for (int e = 0; e < 4; e++)
                if (!(e & eb)) {
                    bool desc = (((cb + wbase + e * 32) & k) == 0);
                    ce_pair(v[e], v[e | eb], desc);
                }
        }
        #pragma unroll
        for (int j = 16; j >= 1; j >>= 1) {
            #pragma unroll
            for (int e = 0; e < 4; e++) {
                bool desc = (((cb + wbase + e * 32 + l) & k) == 0);
                v[e] = shfl_ce(v[e], j, desc == ((l & j) == 0));
            }
        }
    }

    #pragma unroll
    for (int e = 0; e < 4; e++)
        g_keys[(size_t)b * N_ + cb + wbase + e * 32 + l] = v[e];
}

// ---------------------------------------------------------------------------
// K2: k=4096 merge in 4096-windows. grid B*2, block 512, 8 u64/thread.
// ---------------------------------------------------------------------------
__global__ __launch_bounds__(512)
void merge4096_kernel()
{
    __shared__ u64 s[4096];
    const int b    = blockIdx.x >> 1;
    const int base = (blockIdx.x & 1) << 12;
    const bool desc = ((base & 4096) == 0);
    const int t = threadIdx.x;
    const int l = t & 31;
    const int wbase = (t >> 5) << 8;                  // warp*256
    u64* gk = g_keys + (size_t)b * N_ + base;

    for (int x = t; x < 4096; x += 512) s[x] = gk[x];
    __syncthreads();

    #pragma unroll 1
    for (int j = 2048; j >= 256; j >>= 1) {
        #pragma unroll
        for (int q = 0; q < 4; q++) {
            int p = t + q * 512;                          // 0..2047
            int i = ((p & ~(j - 1)) << 1) | (p & (j - 1));
            smem_ce(s, i, i + j, desc);
        }
        __syncthreads();
    }

    u64 v[8];
    #pragma unroll
    for (int e = 0; e < 8; e++) v[e] = s[wbase + e * 32 + l];
    #pragma unroll
    for (int eb = 4; eb >= 1; eb >>= 1)
        #pragma unroll
        for (int e = 0; e < 8; e++)
            if (!(e & eb)) ce_pair(v[e], v[e | eb], desc);
    #pragma unroll
    for (int j = 16; j >= 1; j >>= 1)
        #pragma unroll
        for (int e = 0; e < 8; e++)
            v[e] = shfl_ce(v[e], j, desc == ((l & j) == 0));
    #pragma unroll
    for (int e = 0; e < 8; e++) gk[wbase + e * 32 + l] = v[e];
}

// ---------------------------------------------------------------------------
// K3: k=8192 stages j=4096,2048,1024 as register orbits (desc=true).
// Only the top half survives downstream: after j=4096 the bottom half is
// dead, so stages j=2048/1024 run on the top 4 and only those are written.
// grid B*4, block 256; columns stride 1024, coalesced.
// ---------------------------------------------------------------------------
__global__ __launch_bounds__(256)
void orbit8192_kernel()
{
    const int b = blockIdx.x >> 2;
    const int q = ((blockIdx.x & 3) << 8) + threadIdx.x;   // 0..1023
    u64* gk = g_keys + (size_t)b * N_ + q;

    u64 v[8];
    #pragma unroll
    for (int m = 0; m < 8; m++) v[m] = gk[m << 10];
    #pragma unroll
    for (int m = 0; m < 4; m++) {               // j=4096: keep max in top half
        u64 a = v[m], c = v[m + 4];
        v[m] = a > c ? a : c;
    }
    #pragma unroll
    for (int m = 0; m < 2; m++) ce_pair(v[m], v[m + 2], true);   // j=2048
    ce_pair(v[0], v[1], true);                                    // j=1024
    ce_pair(v[2], v[3], true);
    #pragma unroll
    for (int m = 0; m < 4; m++) gk[m << 10] = v[m];
}

// ---------------------------------------------------------------------------
// K4: final stages j=512..1 in the top-4 1024-windows (desc=true) + emit.
// grid B*4, block 256, 4 u64/thread.
// ---------------------------------------------------------------------------
__global__ __launch_bounds__(256)
void finalize_kernel(float* __restrict__ out_idxf,
                     float* __restrict__ out_scores)
{
    __shared__ u64 s[1024];
    const int b    = blockIdx.x >> 2;
    const int base = (blockIdx.x & 3) << 10;          // rank window base
    const int t = threadIdx.x;
    const int l = t & 31;
    const int wbase = (t >> 5) << 7;
    const u64* gk = g_keys + (size_t)b * N_ + base;

    for (int x = t; x < 1024; x += 256) s[x] = gk[x];
    __syncthreads();

    #pragma unroll 1
    for (int j = 512; j >= 128; j >>= 1) {
        #pragma unroll
        for (int q = 0; q < 2; q++) {
            int p = t + q * 256;
            int i = ((p & ~(j - 1)) << 1) | (p & (j - 1));
            smem_ce(s, i, i + j, true);
        }
        __syncthreads();
    }

    u64 v[4];
    #pragma unroll
    for (int e = 0; e < 4; e++) v[e] = s[wbase + e * 32 + l];
    #pragma unroll
    for (int eb = 2; eb >= 1; eb >>= 1)
        #pragma unroll
        for (int e = 0; e < 4; e++)
            if (!(e & eb)) ce_pair(v[e], v[e | eb], true);
    #pragma unroll
    for (int j = 16; j >= 1; j >>= 1)
        #pragma unroll
        for (int e = 0; e < 4; e++)
            v[e] = shfl_ce(v[e], j, (l & j) == 0);

    #pragma unroll
    for (int e = 0; e < 4; e++) {
        int rank = base + wbase + e * 32 + l;
        u64 x = v[e];
        int idx = 8191 - (int)(x & 0xFFFF);
        unsigned ku = (unsigned)(x >> 16);
        unsigned orig = (ku & 0x80000000u) ? (ku ^ 0x80000000u) : ~ku;
        g_idx[b * K_ + rank] = (unsigned short)idx;
        out_idxf[(size_t)b * K_ + rank]   = (float)idx;
        out_scores[(size_t)b * K_ + rank] = __uint_as_float(orig);
        g_pos[b * N_ + idx] = rank;
    }
}

// ---------------------------------------------------------------------------
// Combined gather: blocks [0,8192) stage one adjacency source row in SMEM and
// serve every batch containing it; blocks [8192,16384) gather features.
// Streaming hints: rows/features read once (.cs), outputs write-once (.cs);
// keeps L2 free for the hot 128KB g_idx.
// ---------------------------------------------------------------------------
__global__ __launch_bounds__(512)
void gather_kernel(const float* __restrict__ A,
                   const float4* __restrict__ feat,
                   float* __restrict__ out_adj,
                   float4* __restrict__ out_feat)
{
    __shared__ float row[N_];   // 32 KB (adj branch only)
    if (blockIdx.x < 8192) {
        const int r = blockIdx.x;
        const float4* src  = (const float4*)(A + (size_t)r * N_);
        float4*       rowv = (float4*)row;
        for (int t = threadIdx.x; t < N_ / 4; t += 512)
            rowv[t] = __ldcs(src + t);
        __syncthreads();

        #pragma unroll 1
        for (int b = 0; b < B_; ++b) {
            int i = g_pos[b * N_ + r];
            if (i < 0) continue;
            float4* obase = (float4*)(out_adj + ((size_t)b * K_ + i) * K_);
            const ushort4* idx4 = (const ushort4*)(g_idx + b * K_);
            for (int t = threadIdx.x; t < K_ / 4; t += 512) {
                ushort4 c = idx4[t];
                __stcs(obase + t,
                       make_float4(row[c.x], row[c.y], row[c.z], row[c.w]));
            }
        }
    } else {
        int o = (blockIdx.x - 8192) * 512 + threadIdx.x;   // 0..4194303
        int frow = o >> 6;                                  // C/4=64 f4/row
        int c    = o & 63;
        int b    = frow >> 12;                              // K rows/batch
        int r    = g_idx[frow];
        __stcs(out_feat + o,
               __ldcs(feat + ((size_t)(b << 13) + r) * 64 + c));
    }
}

// ---------------------------------------------------------------------------
extern "C" void kernel_launch(void* const* d_in, const int* in_sizes, int n_in,
                              void* d_out, int out_size)
{
    const float* scores = (const float*)d_in[0];   // (B, N)
    const float* feat   = (const float*)d_in[1];   // (B, N, C)
    const float* adj    = (const float*)d_in[2];   // (N, N)
    float* out = (float*)d_out;

    float* out_feat   = out + OFF_FEAT;
    float* out_idxf   = out + OFF_IDX;
    float* out_adj    = out + OFF_ADJ;
    float* out_scores = out + OFF_SCORES;

    sort2048_kernel <<<B_ * 4, 512>>>(scores);
    merge4096_kernel<<<B_ * 2, 512>>>();
    orbit8192_kernel<<<B_ * 4, 256>>>();
    finalize_kernel <<<B_ * 4, 256>>>(out_idxf, out_scores);

    gather_kernel<<<16384, 512>>>(adj, (const float4*)feat,
                                  out_adj, (float4*)out_feat);
}